// round 10
// baseline (speedup 1.0000x reference)
#include <cuda_runtime.h>
#include <cstdint>

#define N_NODES 100000
#define N_EDGES 3200000
#define F 128
#define HQ 256
#define ADIM 10
#define NCHUNKS 98   // ceil(100000/1024)

// Scratch (static __device__ arrays: allocation-free per harness rules)
__device__ __align__(16) float g_xw[(size_t)N_NODES * F];   // relu(x@We+be)@Wg
__device__ __align__(16) float g_h2[(size_t)N_NODES * F];   // relu(gcn output)
__device__ float g_dinv[N_NODES];
__device__ int   g_cnt[N_NODES];
__device__ int   g_start[N_NODES + 1];
__device__ int   g_cursor[N_NODES];
__device__ int   g_src[N_EDGES];
__device__ int   g_chunksum[NCHUNKS];
__device__ int   g_chunkoff[NCHUNKS];
__device__ int   g_is64;

// ---- packed f32x2 helpers (Blackwell FFMA2 path) ----
static __device__ __forceinline__ unsigned long long pack2(float lo, float hi) {
    unsigned long long r;
    asm("mov.b64 %0, {%1, %2};" : "=l"(r) : "f"(lo), "f"(hi));
    return r;
}
static __device__ __forceinline__ void fma2(unsigned long long& d,
                                            unsigned long long a,
                                            unsigned long long b) {
    asm("fma.rn.f32x2 %0, %1, %2, %0;" : "+l"(d) : "l"(a), "l"(b));
}
static __device__ __forceinline__ float2 unpack2(unsigned long long v) {
    float2 f;
    asm("mov.b64 {%0, %1}, %2;" : "=f"(f.x), "=f"(f.y) : "l"(v));
    return f;
}

static __device__ __forceinline__ int eidx(const void* ei, int is64, long long pos) {
    return is64 ? (int)((const long long*)ei)[pos] : ((const int*)ei)[pos];
}

// ---- pre: dtype detect (block 0, warp 0) + zero histogram counters ----
__global__ void k_pre(const int* __restrict__ ei) {
    if (blockIdx.x == 0 && threadIdx.x < 32) {
        int v = ei[2 * threadIdx.x + 1];
        unsigned m = __ballot_sync(0xffffffffu, v != 0);
        if (threadIdx.x == 0) g_is64 = (m == 0) ? 1 : 0;
    }
    int i = blockIdx.x * blockDim.x + threadIdx.x;
    int stride = gridDim.x * blockDim.x;
    for (; i < N_NODES; i += stride) g_cnt[i] = 0;
}

// ---- histogram of dst (doubles as in-degree count) ----
__global__ void k_hist(const void* __restrict__ ei) {
    int is64 = g_is64;
    int e = blockIdx.x * blockDim.x + threadIdx.x;
    if (e < N_EDGES) atomicAdd(&g_cnt[eidx(ei, is64, (long long)N_EDGES + e)], 1);
}

// ---- scan stage A: per-1024-chunk sums; also dinv = rsqrt(cnt+1) ----
__global__ void k_scanA() {
    __shared__ int wsum[8];
    int t = threadIdx.x;
    int base = blockIdx.x * 1024 + t * 4;
    int s = 0;
    #pragma unroll
    for (int i = 0; i < 4; i++) {
        int idx = base + i;
        if (idx < N_NODES) {
            int c = g_cnt[idx];
            s += c;
            g_dinv[idx] = rsqrtf((float)(c + 1));
        }
    }
    #pragma unroll
    for (int o = 16; o > 0; o >>= 1) s += __shfl_down_sync(0xffffffffu, s, o);
    if ((t & 31) == 0) wsum[t >> 5] = s;
    __syncthreads();
    if (t == 0) {
        int tot = 0;
        #pragma unroll
        for (int w = 0; w < 8; w++) tot += wsum[w];
        g_chunksum[blockIdx.x] = tot;
    }
}

// ---- scan stage B: exclusive scan of chunk sums ----
__global__ void k_scanB() {
    __shared__ int sv[NCHUNKS];
    int t = threadIdx.x;
    if (t < NCHUNKS) sv[t] = g_chunksum[t];
    __syncthreads();
    if (t == 0) {
        int acc = 0;
        for (int b = 0; b < NCHUNKS; b++) { int x = sv[b]; sv[b] = acc; acc += x; }
        g_start[N_NODES] = acc;
    }
    __syncthreads();
    if (t < NCHUNKS) g_chunkoff[t] = sv[t];
}

// ---- scan stage C: within-chunk exclusive scan -> start, cursor ----
__global__ void k_scanC() {
    __shared__ int wsum[8];
    int t = threadIdx.x;
    int lane = t & 31, wid = t >> 5;
    int base = blockIdx.x * 1024 + t * 4;
    int v[4];
    int s = 0;
    #pragma unroll
    for (int i = 0; i < 4; i++) {
        int idx = base + i;
        v[i] = (idx < N_NODES) ? g_cnt[idx] : 0;
        s += v[i];
    }
    int inc = s;
    #pragma unroll
    for (int o = 1; o < 32; o <<= 1) {
        int n = __shfl_up_sync(0xffffffffu, inc, o);
        if (lane >= o) inc += n;
    }
    if (lane == 31) wsum[wid] = inc;
    __syncthreads();
    if (t == 0) {
        int acc = 0;
        #pragma unroll
        for (int w = 0; w < 8; w++) { int x = wsum[w]; wsum[w] = acc; acc += x; }
    }
    __syncthreads();
    int excl = inc - s + wsum[wid] + g_chunkoff[blockIdx.x];
    #pragma unroll
    for (int i = 0; i < 4; i++) {
        int idx = base + i;
        if (idx < N_NODES) { g_start[idx] = excl; g_cursor[idx] = excl; }
        excl += v[i];
    }
}

// ---- permute edges into dst-grouped order ----
__global__ void k_permute(const void* __restrict__ ei) {
    int is64 = g_is64;
    int e = blockIdx.x * blockDim.x + threadIdx.x;
    if (e < N_EDGES) {
        int s = eidx(ei, is64, e);
        int d = eidx(ei, is64, (long long)N_EDGES + e);
        int pos = atomicAdd(&g_cursor[d], 1);
        g_src[pos] = s;
    }
}

// ==================== fused1: xw = relu(x@We + be) @ Wg ====================
#define XT_S 132

__global__ void __launch_bounds__(256, 1)
k_fused1(const float* __restrict__ x, const float* __restrict__ We,
         const float* __restrict__ be, const float* __restrict__ Wg) {
    extern __shared__ float smem[];
    float* sW  = smem;                    // 128*128
    float* sXT = smem + 16384;            // 128 * XT_S
    float* sHT = sXT + 128 * XT_S;        // 128 * XT_S
    float* sBe = sHT + 128 * XT_S;        // 128

    const int tid = threadIdx.x;
    const int base = blockIdx.x * 128;

    for (int idx = tid; idx < 16384; idx += 256) sW[idx] = We[idx];
    if (tid < 128) sBe[tid] = be[tid];
    for (int idx = tid; idx < 128 * F; idx += 256) {
        int r = idx >> 7, c = idx & 127;
        int node = base + r;
        sXT[c * XT_S + r] = (node < N_NODES) ? x[(size_t)node * F + c] : 0.f;
    }
    __syncthreads();

    const int tr = tid & 15, tc = tid >> 4;
    const int r0 = tr * 8, c0 = tc * 8;

    unsigned long long acc[8][4];
    #pragma unroll
    for (int ri = 0; ri < 8; ri++)
        #pragma unroll
        for (int cj = 0; cj < 4; cj++)
            acc[ri][cj] = pack2(sBe[c0 + 2 * cj], sBe[c0 + 2 * cj + 1]);

    #pragma unroll 4
    for (int k = 0; k < F; k++) {
        float4 a0 = *(const float4*)&sXT[k * XT_S + r0];
        float4 a1 = *(const float4*)&sXT[k * XT_S + r0 + 4];
        float4 w0 = *(const float4*)&sW[k * F + c0];
        float4 w1 = *(const float4*)&sW[k * F + c0 + 4];
        unsigned long long w[4] = { pack2(w0.x, w0.y), pack2(w0.z, w0.w),
                                    pack2(w1.x, w1.y), pack2(w1.z, w1.w) };
        float a[8] = {a0.x, a0.y, a0.z, a0.w, a1.x, a1.y, a1.z, a1.w};
        #pragma unroll
        for (int ri = 0; ri < 8; ri++) {
            unsigned long long av = pack2(a[ri], a[ri]);
            #pragma unroll
            for (int cj = 0; cj < 4; cj++) fma2(acc[ri][cj], av, w[cj]);
        }
    }

    #pragma unroll
    for (int cj = 0; cj < 4; cj++) {
        float2 v[8];
        #pragma unroll
        for (int ri = 0; ri < 8; ri++) v[ri] = unpack2(acc[ri][cj]);
        int c = c0 + 2 * cj;
        *(float4*)&sHT[c * XT_S + r0] =
            make_float4(fmaxf(v[0].x, 0.f), fmaxf(v[1].x, 0.f),
                        fmaxf(v[2].x, 0.f), fmaxf(v[3].x, 0.f));
        *(float4*)&sHT[c * XT_S + r0 + 4] =
            make_float4(fmaxf(v[4].x, 0.f), fmaxf(v[5].x, 0.f),
                        fmaxf(v[6].x, 0.f), fmaxf(v[7].x, 0.f));
        *(float4*)&sHT[(c + 1) * XT_S + r0] =
            make_float4(fmaxf(v[0].y, 0.f), fmaxf(v[1].y, 0.f),
                        fmaxf(v[2].y, 0.f), fmaxf(v[3].y, 0.f));
        *(float4*)&sHT[(c + 1) * XT_S + r0 + 4] =
            make_float4(fmaxf(v[4].y, 0.f), fmaxf(v[5].y, 0.f),
                        fmaxf(v[6].y, 0.f), fmaxf(v[7].y, 0.f));
    }
    __syncthreads();
    for (int idx = tid; idx < 16384; idx += 256) sW[idx] = Wg[idx];
    __syncthreads();

    #pragma unroll
    for (int ri = 0; ri < 8; ri++)
        #pragma unroll
        for (int cj = 0; cj < 4; cj++) acc[ri][cj] = 0ULL;

    #pragma unroll 4
    for (int k = 0; k < F; k++) {
        float4 a0 = *(const float4*)&sHT[k * XT_S + r0];
        float4 a1 = *(const float4*)&sHT[k * XT_S + r0 + 4];
        float4 w0 = *(const float4*)&sW[k * F + c0];
        float4 w1 = *(const float4*)&sW[k * F + c0 + 4];
        unsigned long long w[4] = { pack2(w0.x, w0.y), pack2(w0.z, w0.w),
                                    pack2(w1.x, w1.y), pack2(w1.z, w1.w) };
        float a[8] = {a0.x, a0.y, a0.z, a0.w, a1.x, a1.y, a1.z, a1.w};
        #pragma unroll
        for (int ri = 0; ri < 8; ri++) {
            unsigned long long av = pack2(a[ri], a[ri]);
            #pragma unroll
            for (int cj = 0; cj < 4; cj++) fma2(acc[ri][cj], av, w[cj]);
        }
    }

    #pragma unroll
    for (int ri = 0; ri < 8; ri++) {
        int node = base + r0 + ri;
        if (node < N_NODES) {
            float* dst = &g_xw[(size_t)node * F + c0];
            *(ulonglong2*)(dst)     = make_ulonglong2(acc[ri][0], acc[ri][1]);
            *(ulonglong2*)(dst + 4) = make_ulonglong2(acc[ri][2], acc[ri][3]);
        }
    }
}

// ============ aggregate (feature-split): one 64-feature half per pass ============
// Working set of gathered xw half = 25.6MB -> L2-resident.
// Warp per node; lanes split into 2 sub-groups of 16, each handling one edge;
// each sub-lane loads one float4 (16 slots * 16B = 256B half-row).
__global__ void __launch_bounds__(256)
k_aggregate_half(const float* __restrict__ bg, int pass) {
    int warp = (blockIdx.x * blockDim.x + threadIdx.x) >> 5;
    int lane = threadIdx.x & 31;
    if (warp >= N_NODES) return;

    const int sub  = lane >> 4;   // 0/1: which edge of the pair
    const int slot = lane & 15;   // float4 slot within the 64-float half
    const int fb   = pass * 16;   // float4 offset within the 32-float4 row
    const float4* xw4 = reinterpret_cast<const float4*>(g_xw);

    int j0 = g_start[warp], j1 = g_start[warp + 1];

    float4 a0 = make_float4(0.f, 0.f, 0.f, 0.f);
    float4 a1 = a0, a2 = a0, a3 = a0;

    int j = j0;
    for (; j + 8 <= j1; j += 8) {
        int e0 = j + sub, e1 = j + 2 + sub, e2 = j + 4 + sub, e3 = j + 6 + sub;
        int s0 = __ldcs(&g_src[e0]);
        int s1 = __ldcs(&g_src[e1]);
        int s2 = __ldcs(&g_src[e2]);
        int s3 = __ldcs(&g_src[e3]);
        float c0 = __ldg(&g_dinv[s0]);
        float c1 = __ldg(&g_dinv[s1]);
        float c2 = __ldg(&g_dinv[s2]);
        float c3 = __ldg(&g_dinv[s3]);
        float4 v0 = __ldg(&xw4[(size_t)s0 * 32 + fb + slot]);
        float4 v1 = __ldg(&xw4[(size_t)s1 * 32 + fb + slot]);
        float4 v2 = __ldg(&xw4[(size_t)s2 * 32 + fb + slot]);
        float4 v3 = __ldg(&xw4[(size_t)s3 * 32 + fb + slot]);
        a0.x += v0.x * c0; a0.y += v0.y * c0; a0.z += v0.z * c0; a0.w += v0.w * c0;
        a1.x += v1.x * c1; a1.y += v1.y * c1; a1.z += v1.z * c1; a1.w += v1.w * c1;
        a2.x += v2.x * c2; a2.y += v2.y * c2; a2.z += v2.z * c2; a2.w += v2.w * c2;
        a3.x += v3.x * c3; a3.y += v3.y * c3; a3.z += v3.z * c3; a3.w += v3.w * c3;
    }
    for (; j < j1; j += 2) {
        int e = j + sub;
        if (e < j1) {
            int s = __ldcs(&g_src[e]);
            float c = __ldg(&g_dinv[s]);
            float4 v = __ldg(&xw4[(size_t)s * 32 + fb + slot]);
            a0.x += v.x * c; a0.y += v.y * c; a0.z += v.z * c; a0.w += v.w * c;
        }
    }
    float4 acc = make_float4(a0.x + a1.x + a2.x + a3.x,
                             a0.y + a1.y + a2.y + a3.y,
                             a0.z + a1.z + a2.z + a3.z,
                             a0.w + a1.w + a2.w + a3.w);
    // merge the two sub-groups (same slot, lane ^ 16)
    acc.x += __shfl_xor_sync(0xffffffffu, acc.x, 16);
    acc.y += __shfl_xor_sync(0xffffffffu, acc.y, 16);
    acc.z += __shfl_xor_sync(0xffffffffu, acc.z, 16);
    acc.w += __shfl_xor_sync(0xffffffffu, acc.w, 16);

    if (sub == 0) {
        float dd = g_dinv[warp];
        float dd2 = dd * dd;
        float4 self = __ldg(&xw4[(size_t)warp * 32 + fb + slot]);
        float4 bgv = *reinterpret_cast<const float4*>(&bg[pass * 64 + slot * 4]);
        float4 h;
        h.x = fmaxf(dd * acc.x + dd2 * self.x + bgv.x, 0.f);
        h.y = fmaxf(dd * acc.y + dd2 * self.y + bgv.y, 0.f);
        h.z = fmaxf(dd * acc.z + dd2 * self.z + bgv.z, 0.f);
        h.w = fmaxf(dd * acc.w + dd2 * self.w + bgv.w, 0.f);
        reinterpret_cast<float4*>(g_h2)[(size_t)warp * 32 + fb + slot] = h;
    }
}

// ==================== fused2: out = relu(h2@W1+b1)@W2+b2 ====================
#define HT_S 68

__global__ void __launch_bounds__(256, 1)
k_fused2(const float* __restrict__ W1, const float* __restrict__ b1,
         const float* __restrict__ W2, const float* __restrict__ b2,
         float* __restrict__ out) {
    extern __shared__ float smem[];
    float* sW1  = smem;                   // 32768
    float* sHT  = sW1 + 32768;            // 128 * HT_S
    float* sW2  = sHT + 128 * HT_S;       // 2560
    float* sB1  = sW2 + 2560;             // 256
    float* sB2  = sB1 + 256;              // 16
    float* sOut = sB2 + 16;               // 8 * 640

    const int tid = threadIdx.x;
    const int base = blockIdx.x * 64;

    for (int idx = tid; idx < 32768; idx += 256) sW1[idx] = W1[idx];
    for (int idx = tid; idx < 2560; idx += 256) sW2[idx] = W2[idx];
    sB1[tid] = b1[tid];
    if (tid < ADIM) sB2[tid] = b2[tid];

    for (int idx = tid; idx < 64 * F; idx += 256) {
        int r = idx >> 7, c = idx & 127;
        int node = base + r;
        sHT[c * HT_S + r] = (node < N_NODES) ? g_h2[(size_t)node * F + c] : 0.f;
    }
    __syncthreads();

    const int tr = tid & 7, tc = tid >> 3;
    const int r0 = tr * 8, c0 = tc * 8;
    const int lane = tid & 31, wrp = tid >> 5;

    unsigned long long acc[8][4];
    #pragma unroll
    for (int ri = 0; ri < 8; ri++)
        #pragma unroll
        for (int cj = 0; cj < 4; cj++)
            acc[ri][cj] = pack2(sB1[c0 + 2 * cj], sB1[c0 + 2 * cj + 1]);

    #pragma unroll 4
    for (int k = 0; k < F; k++) {
        float4 a0 = *(const float4*)&sHT[k * HT_S + r0];
        float4 a1 = *(const float4*)&sHT[k * HT_S + r0 + 4];
        float4 w0 = *(const float4*)&sW1[k * HQ + c0];
        float4 w1 = *(const float4*)&sW1[k * HQ + c0 + 4];
        unsigned long long w[4] = { pack2(w0.x, w0.y), pack2(w0.z, w0.w),
                                    pack2(w1.x, w1.y), pack2(w1.z, w1.w) };
        float a[8] = {a0.x, a0.y, a0.z, a0.w, a1.x, a1.y, a1.z, a1.w};
        #pragma unroll
        for (int ri = 0; ri < 8; ri++) {
            unsigned long long av = pack2(a[ri], a[ri]);
            #pragma unroll
            for (int cj = 0; cj < 4; cj++) fma2(acc[ri][cj], av, w[cj]);
        }
    }

    #pragma unroll
    for (int ri = 0; ri < 8; ri++) {
        float p[ADIM];
        #pragma unroll
        for (int a = 0; a < ADIM; a++) p[a] = 0.f;
        #pragma unroll
        for (int cj = 0; cj < 4; cj++) {
            float2 q = unpack2(acc[ri][cj]);
            q.x = fmaxf(q.x, 0.f);
            q.y = fmaxf(q.y, 0.f);
            const float* wa = &sW2[(c0 + 2 * cj) * ADIM];
            #pragma unroll
            for (int a = 0; a < ADIM; a++)
                p[a] += q.x * wa[a] + q.y * wa[ADIM + a];
        }
        #pragma unroll
        for (int a = 0; a < ADIM; a++) {
            p[a] += __shfl_xor_sync(0xffffffffu, p[a], 8);
            p[a] += __shfl_xor_sync(0xffffffffu, p[a], 16);
        }
        if (lane < 8) {
            int row = r0 + ri;
            #pragma unroll
            for (int a = 0; a < ADIM; a++)
                sOut[wrp * 640 + row * ADIM + a] = p[a];
        }
    }
    __syncthreads();

    for (int idx = tid; idx < 64 * ADIM; idx += 256) {
        float v = 0.f;
        #pragma unroll
        for (int w = 0; w < 8; w++) v += sOut[w * 640 + idx];
        int row = idx / ADIM, a = idx - row * ADIM;
        int node = base + row;
        if (node < N_NODES) out[(size_t)node * ADIM + a] = v + sB2[a];
    }
}

extern "C" void kernel_launch(void* const* d_in, const int* in_sizes, int n_in,
                              void* d_out, int out_size) {
    const float* x  = (const float*)d_in[0];
    const void*  ei = d_in[1];
    const float* We = (const float*)d_in[2];
    const float* be = (const float*)d_in[3];
    const float* Wg = (const float*)d_in[4];
    const float* bg = (const float*)d_in[5];
    const float* W1 = (const float*)d_in[6];
    const float* b1 = (const float*)d_in[7];
    const float* W2 = (const float*)d_in[8];
    const float* b2 = (const float*)d_in[9];
    float* out = (float*)d_out;

    const size_t smemA = (size_t)(16384 + 2 * 128 * XT_S + 128) * sizeof(float);
    const size_t smemC = (size_t)(32768 + 128 * HT_S + 2560 + 256 + 16 + 5120) * sizeof(float);
    cudaFuncSetAttribute(k_fused1, cudaFuncAttributeMaxDynamicSharedMemorySize, (int)smemA);
    cudaFuncSetAttribute(k_fused2, cudaFuncAttributeMaxDynamicSharedMemorySize, (int)smemC);

    const int aggBlocks = (N_NODES * 32 + 255) / 256;

    k_pre<<<98, 1024>>>((const int*)ei);
    k_fused1<<<(N_NODES + 127) / 128, 256, smemA>>>(x, We, be, Wg);
    k_hist<<<(N_EDGES + 255) / 256, 256>>>(ei);
    k_scanA<<<NCHUNKS, 256>>>();
    k_scanB<<<1, 128>>>();
    k_scanC<<<NCHUNKS, 256>>>();
    k_permute<<<(N_EDGES + 255) / 256, 256>>>(ei);
    k_aggregate_half<<<aggBlocks, 256>>>(bg, 0);
    k_aggregate_half<<<aggBlocks, 256>>>(bg, 1);
    k_fused2<<<(N_NODES + 63) / 64, 256, smemC>>>(W1, b1, W2, b2, out);
}

// round 11
// speedup vs baseline: 1.5809x; 1.5809x over previous
#include <cuda_runtime.h>
#include <cuda_bf16.h>
#include <cstdint>

#define N_NODES 100000
#define N_EDGES 3200000
#define F 128
#define HQ 256
#define ADIM 10
#define NCHUNKS 98   // ceil(100000/1024)

// Scratch (static __device__ arrays: allocation-free per harness rules)
__device__ __align__(16) float g_xw[(size_t)N_NODES * F];          // fp32 xw (self term)
__device__ __align__(16) __nv_bfloat16 g_xwh[(size_t)N_NODES * F]; // bf16 xw (gathers)
__device__ __align__(16) float g_h2[(size_t)N_NODES * F];          // relu(gcn output)
__device__ float g_dinv[N_NODES];
__device__ int   g_cnt[N_NODES];
__device__ int   g_start[N_NODES + 1];
__device__ int   g_cursor[N_NODES];
__device__ int   g_src[N_EDGES];
__device__ int   g_chunksum[NCHUNKS];
__device__ int   g_chunkoff[NCHUNKS];
__device__ int   g_is64;

// ---- packed f32x2 helpers (Blackwell FFMA2 path) ----
static __device__ __forceinline__ unsigned long long pack2(float lo, float hi) {
    unsigned long long r;
    asm("mov.b64 %0, {%1, %2};" : "=l"(r) : "f"(lo), "f"(hi));
    return r;
}
static __device__ __forceinline__ void fma2(unsigned long long& d,
                                            unsigned long long a,
                                            unsigned long long b) {
    asm("fma.rn.f32x2 %0, %1, %2, %0;" : "+l"(d) : "l"(a), "l"(b));
}
static __device__ __forceinline__ float2 unpack2(unsigned long long v) {
    float2 f;
    asm("mov.b64 {%0, %1}, %2;" : "=f"(f.x), "=f"(f.y) : "l"(v));
    return f;
}

static __device__ __forceinline__ int eidx(const void* ei, int is64, long long pos) {
    return is64 ? (int)((const long long*)ei)[pos] : ((const int*)ei)[pos];
}

static __device__ __forceinline__ float4 bf8_to_f4(uint2 u) {
    __nv_bfloat162 p0 = *reinterpret_cast<__nv_bfloat162*>(&u.x);
    __nv_bfloat162 p1 = *reinterpret_cast<__nv_bfloat162*>(&u.y);
    float2 f0 = __bfloat1622float2(p0);
    float2 f1 = __bfloat1622float2(p1);
    return make_float4(f0.x, f0.y, f1.x, f1.y);
}

// ---- pre: dtype detect (block 0, warp 0) + zero histogram counters ----
__global__ void k_pre(const int* __restrict__ ei) {
    if (blockIdx.x == 0 && threadIdx.x < 32) {
        int v = ei[2 * threadIdx.x + 1];
        unsigned m = __ballot_sync(0xffffffffu, v != 0);
        if (threadIdx.x == 0) g_is64 = (m == 0) ? 1 : 0;
    }
    int i = blockIdx.x * blockDim.x + threadIdx.x;
    int stride = gridDim.x * blockDim.x;
    for (; i < N_NODES; i += stride) g_cnt[i] = 0;
}

// ---- histogram of dst (doubles as in-degree count) ----
__global__ void k_hist(const void* __restrict__ ei) {
    int is64 = g_is64;
    int e = blockIdx.x * blockDim.x + threadIdx.x;
    if (e < N_EDGES) atomicAdd(&g_cnt[eidx(ei, is64, (long long)N_EDGES + e)], 1);
}

// ---- scan stage A: per-1024-chunk sums; also dinv = rsqrt(cnt+1) ----
__global__ void k_scanA() {
    __shared__ int wsum[8];
    int t = threadIdx.x;
    int base = blockIdx.x * 1024 + t * 4;
    int s = 0;
    #pragma unroll
    for (int i = 0; i < 4; i++) {
        int idx = base + i;
        if (idx < N_NODES) {
            int c = g_cnt[idx];
            s += c;
            g_dinv[idx] = rsqrtf((float)(c + 1));
        }
    }
    #pragma unroll
    for (int o = 16; o > 0; o >>= 1) s += __shfl_down_sync(0xffffffffu, s, o);
    if ((t & 31) == 0) wsum[t >> 5] = s;
    __syncthreads();
    if (t == 0) {
        int tot = 0;
        #pragma unroll
        for (int w = 0; w < 8; w++) tot += wsum[w];
        g_chunksum[blockIdx.x] = tot;
    }
}

// ---- scan stage B: exclusive scan of chunk sums ----
__global__ void k_scanB() {
    __shared__ int sv[NCHUNKS];
    int t = threadIdx.x;
    if (t < NCHUNKS) sv[t] = g_chunksum[t];
    __syncthreads();
    if (t == 0) {
        int acc = 0;
        for (int b = 0; b < NCHUNKS; b++) { int x = sv[b]; sv[b] = acc; acc += x; }
        g_start[N_NODES] = acc;
    }
    __syncthreads();
    if (t < NCHUNKS) g_chunkoff[t] = sv[t];
}

// ---- scan stage C: within-chunk exclusive scan -> start, cursor ----
__global__ void k_scanC() {
    __shared__ int wsum[8];
    int t = threadIdx.x;
    int lane = t & 31, wid = t >> 5;
    int base = blockIdx.x * 1024 + t * 4;
    int v[4];
    int s = 0;
    #pragma unroll
    for (int i = 0; i < 4; i++) {
        int idx = base + i;
        v[i] = (idx < N_NODES) ? g_cnt[idx] : 0;
        s += v[i];
    }
    int inc = s;
    #pragma unroll
    for (int o = 1; o < 32; o <<= 1) {
        int n = __shfl_up_sync(0xffffffffu, inc, o);
        if (lane >= o) inc += n;
    }
    if (lane == 31) wsum[wid] = inc;
    __syncthreads();
    if (t == 0) {
        int acc = 0;
        #pragma unroll
        for (int w = 0; w < 8; w++) { int x = wsum[w]; wsum[w] = acc; acc += x; }
    }
    __syncthreads();
    int excl = inc - s + wsum[wid] + g_chunkoff[blockIdx.x];
    #pragma unroll
    for (int i = 0; i < 4; i++) {
        int idx = base + i;
        if (idx < N_NODES) { g_start[idx] = excl; g_cursor[idx] = excl; }
        excl += v[i];
    }
}

// ---- permute edges into dst-grouped order ----
__global__ void k_permute(const void* __restrict__ ei) {
    int is64 = g_is64;
    int e = blockIdx.x * blockDim.x + threadIdx.x;
    if (e < N_EDGES) {
        int s = eidx(ei, is64, e);
        int d = eidx(ei, is64, (long long)N_EDGES + e);
        int pos = atomicAdd(&g_cursor[d], 1);
        g_src[pos] = s;
    }
}

// ==================== fused1: xw = relu(x@We + be) @ Wg (fp32 + bf16 copies) ====================
#define XT_S 132

__global__ void __launch_bounds__(256, 1)
k_fused1(const float* __restrict__ x, const float* __restrict__ We,
         const float* __restrict__ be, const float* __restrict__ Wg) {
    extern __shared__ float smem[];
    float* sW  = smem;                    // 128*128
    float* sXT = smem + 16384;            // 128 * XT_S
    float* sHT = sXT + 128 * XT_S;        // 128 * XT_S
    float* sBe = sHT + 128 * XT_S;        // 128

    const int tid = threadIdx.x;
    const int base = blockIdx.x * 128;

    for (int idx = tid; idx < 16384; idx += 256) sW[idx] = We[idx];
    if (tid < 128) sBe[tid] = be[tid];
    for (int idx = tid; idx < 128 * F; idx += 256) {
        int r = idx >> 7, c = idx & 127;
        int node = base + r;
        sXT[c * XT_S + r] = (node < N_NODES) ? x[(size_t)node * F + c] : 0.f;
    }
    __syncthreads();

    const int tr = tid & 15, tc = tid >> 4;
    const int r0 = tr * 8, c0 = tc * 8;

    unsigned long long acc[8][4];
    #pragma unroll
    for (int ri = 0; ri < 8; ri++)
        #pragma unroll
        for (int cj = 0; cj < 4; cj++)
            acc[ri][cj] = pack2(sBe[c0 + 2 * cj], sBe[c0 + 2 * cj + 1]);

    #pragma unroll 4
    for (int k = 0; k < F; k++) {
        float4 a0 = *(const float4*)&sXT[k * XT_S + r0];
        float4 a1 = *(const float4*)&sXT[k * XT_S + r0 + 4];
        float4 w0 = *(const float4*)&sW[k * F + c0];
        float4 w1 = *(const float4*)&sW[k * F + c0 + 4];
        unsigned long long w[4] = { pack2(w0.x, w0.y), pack2(w0.z, w0.w),
                                    pack2(w1.x, w1.y), pack2(w1.z, w1.w) };
        float a[8] = {a0.x, a0.y, a0.z, a0.w, a1.x, a1.y, a1.z, a1.w};
        #pragma unroll
        for (int ri = 0; ri < 8; ri++) {
            unsigned long long av = pack2(a[ri], a[ri]);
            #pragma unroll
            for (int cj = 0; cj < 4; cj++) fma2(acc[ri][cj], av, w[cj]);
        }
    }

    #pragma unroll
    for (int cj = 0; cj < 4; cj++) {
        float2 v[8];
        #pragma unroll
        for (int ri = 0; ri < 8; ri++) v[ri] = unpack2(acc[ri][cj]);
        int c = c0 + 2 * cj;
        *(float4*)&sHT[c * XT_S + r0] =
            make_float4(fmaxf(v[0].x, 0.f), fmaxf(v[1].x, 0.f),
                        fmaxf(v[2].x, 0.f), fmaxf(v[3].x, 0.f));
        *(float4*)&sHT[c * XT_S + r0 + 4] =
            make_float4(fmaxf(v[4].x, 0.f), fmaxf(v[5].x, 0.f),
                        fmaxf(v[6].x, 0.f), fmaxf(v[7].x, 0.f));
        *(float4*)&sHT[(c + 1) * XT_S + r0] =
            make_float4(fmaxf(v[0].y, 0.f), fmaxf(v[1].y, 0.f),
                        fmaxf(v[2].y, 0.f), fmaxf(v[3].y, 0.f));
        *(float4*)&sHT[(c + 1) * XT_S + r0 + 4] =
            make_float4(fmaxf(v[4].y, 0.f), fmaxf(v[5].y, 0.f),
                        fmaxf(v[6].y, 0.f), fmaxf(v[7].y, 0.f));
    }
    __syncthreads();
    for (int idx = tid; idx < 16384; idx += 256) sW[idx] = Wg[idx];
    __syncthreads();

    #pragma unroll
    for (int ri = 0; ri < 8; ri++)
        #pragma unroll
        for (int cj = 0; cj < 4; cj++) acc[ri][cj] = 0ULL;

    #pragma unroll 4
    for (int k = 0; k < F; k++) {
        float4 a0 = *(const float4*)&sHT[k * XT_S + r0];
        float4 a1 = *(const float4*)&sHT[k * XT_S + r0 + 4];
        float4 w0 = *(const float4*)&sW[k * F + c0];
        float4 w1 = *(const float4*)&sW[k * F + c0 + 4];
        unsigned long long w[4] = { pack2(w0.x, w0.y), pack2(w0.z, w0.w),
                                    pack2(w1.x, w1.y), pack2(w1.z, w1.w) };
        float a[8] = {a0.x, a0.y, a0.z, a0.w, a1.x, a1.y, a1.z, a1.w};
        #pragma unroll
        for (int ri = 0; ri < 8; ri++) {
            unsigned long long av = pack2(a[ri], a[ri]);
            #pragma unroll
            for (int cj = 0; cj < 4; cj++) fma2(acc[ri][cj], av, w[cj]);
        }
    }

    #pragma unroll
    for (int ri = 0; ri < 8; ri++) {
        int node = base + r0 + ri;
        if (node < N_NODES) {
            float* dst = &g_xw[(size_t)node * F + c0];
            *(ulonglong2*)(dst)     = make_ulonglong2(acc[ri][0], acc[ri][1]);
            *(ulonglong2*)(dst + 4) = make_ulonglong2(acc[ri][2], acc[ri][3]);
            // bf16 copy: 8 cols -> 4x bfloat162 = one 16B store
            float2 p0 = unpack2(acc[ri][0]);
            float2 p1 = unpack2(acc[ri][1]);
            float2 p2 = unpack2(acc[ri][2]);
            float2 p3 = unpack2(acc[ri][3]);
            __nv_bfloat162 b0 = __float22bfloat162_rn(p0);
            __nv_bfloat162 b1 = __float22bfloat162_rn(p1);
            __nv_bfloat162 b2 = __float22bfloat162_rn(p2);
            __nv_bfloat162 b3 = __float22bfloat162_rn(p3);
            uint4 pk;
            pk.x = *reinterpret_cast<unsigned*>(&b0);
            pk.y = *reinterpret_cast<unsigned*>(&b1);
            pk.z = *reinterpret_cast<unsigned*>(&b2);
            pk.w = *reinterpret_cast<unsigned*>(&b3);
            *reinterpret_cast<uint4*>(&g_xwh[(size_t)node * F + c0]) = pk;
        }
    }
}

// ==================== aggregate: warp-per-node segment sum (bf16 gathers) ====================
// h2[d] = relu( dinv[d] * sum_j dinv[src_j]*xwh[src_j] + dinv[d]^2 * xw[d] + bg )
__global__ void __launch_bounds__(256)
k_aggregate(const float* __restrict__ bg) {
    int warp = (blockIdx.x * blockDim.x + threadIdx.x) >> 5;
    int lane = threadIdx.x & 31;
    if (warp >= N_NODES) return;

    const uint2* xh = reinterpret_cast<const uint2*>(g_xwh);  // 32 x uint2 per row
    int j0 = g_start[warp], j1 = g_start[warp + 1];

    float4 a0 = make_float4(0.f, 0.f, 0.f, 0.f);
    float4 a1 = a0, a2 = a0, a3 = a0;

    int j = j0;
    for (; j + 8 <= j1; j += 8) {
        int   si[8];
        float ci[8];
        #pragma unroll
        for (int u = 0; u < 8; u++) si[u] = __ldg(&g_src[j + u]);
        #pragma unroll
        for (int u = 0; u < 8; u++) ci[u] = __ldg(&g_dinv[si[u]]);
        uint2 rv[8];
        #pragma unroll
        for (int u = 0; u < 8; u++) rv[u] = __ldg(&xh[(size_t)si[u] * 32 + lane]);
        #pragma unroll
        for (int u = 0; u < 8; u++) {
            float4 v = bf8_to_f4(rv[u]);
            float c = ci[u];
            float4& a = (u & 3) == 0 ? a0 : (u & 3) == 1 ? a1 : (u & 3) == 2 ? a2 : a3;
            a.x += v.x * c; a.y += v.y * c; a.z += v.z * c; a.w += v.w * c;
        }
    }
    for (; j < j1; j++) {
        int s = __ldg(&g_src[j]);
        float c = __ldg(&g_dinv[s]);
        float4 v = bf8_to_f4(__ldg(&xh[(size_t)s * 32 + lane]));
        a0.x += v.x * c; a0.y += v.y * c; a0.z += v.z * c; a0.w += v.w * c;
    }
    float4 acc = make_float4(a0.x + a1.x + a2.x + a3.x,
                             a0.y + a1.y + a2.y + a3.y,
                             a0.z + a1.z + a2.z + a3.z,
                             a0.w + a1.w + a2.w + a3.w);

    float dd = g_dinv[warp];
    float dd2 = dd * dd;
    // self term in fp32; lane covers floats [lane*4, lane*4+4)
    float4 self = __ldg(&reinterpret_cast<const float4*>(g_xw)[(size_t)warp * 32 + lane]);
    float4 bgv = *reinterpret_cast<const float4*>(&bg[lane * 4]);
    float4 h;
    h.x = fmaxf(dd * acc.x + dd2 * self.x + bgv.x, 0.f);
    h.y = fmaxf(dd * acc.y + dd2 * self.y + bgv.y, 0.f);
    h.z = fmaxf(dd * acc.z + dd2 * self.z + bgv.z, 0.f);
    h.w = fmaxf(dd * acc.w + dd2 * self.w + bgv.w, 0.f);
    reinterpret_cast<float4*>(g_h2)[(size_t)warp * 32 + lane] = h;
}

// ==================== fused2: out = relu(h2@W1+b1)@W2+b2 ====================
#define HT_S 68

__global__ void __launch_bounds__(256, 1)
k_fused2(const float* __restrict__ W1, const float* __restrict__ b1,
         const float* __restrict__ W2, const float* __restrict__ b2,
         float* __restrict__ out) {
    extern __shared__ float smem[];
    float* sW1  = smem;                   // 32768
    float* sHT  = sW1 + 32768;            // 128 * HT_S
    float* sW2  = sHT + 128 * HT_S;       // 2560
    float* sB1  = sW2 + 2560;             // 256
    float* sB2  = sB1 + 256;              // 16
    float* sOut = sB2 + 16;               // 8 * 640

    const int tid = threadIdx.x;
    const int base = blockIdx.x * 64;

    for (int idx = tid; idx < 32768; idx += 256) sW1[idx] = W1[idx];
    for (int idx = tid; idx < 2560; idx += 256) sW2[idx] = W2[idx];
    sB1[tid] = b1[tid];
    if (tid < ADIM) sB2[tid] = b2[tid];

    for (int idx = tid; idx < 64 * F; idx += 256) {
        int r = idx >> 7, c = idx & 127;
        int node = base + r;
        sHT[c * HT_S + r] = (node < N_NODES) ? g_h2[(size_t)node * F + c] : 0.f;
    }
    __syncthreads();

    const int tr = tid & 7, tc = tid >> 3;
    const int r0 = tr * 8, c0 = tc * 8;
    const int lane = tid & 31, wrp = tid >> 5;

    unsigned long long acc[8][4];
    #pragma unroll
    for (int ri = 0; ri < 8; ri++)
        #pragma unroll
        for (int cj = 0; cj < 4; cj++)
            acc[ri][cj] = pack2(sB1[c0 + 2 * cj], sB1[c0 + 2 * cj + 1]);

    #pragma unroll 4
    for (int k = 0; k < F; k++) {
        float4 a0 = *(const float4*)&sHT[k * HT_S + r0];
        float4 a1 = *(const float4*)&sHT[k * HT_S + r0 + 4];
        float4 w0 = *(const float4*)&sW1[k * HQ + c0];
        float4 w1 = *(const float4*)&sW1[k * HQ + c0 + 4];
        unsigned long long w[4] = { pack2(w0.x, w0.y), pack2(w0.z, w0.w),
                                    pack2(w1.x, w1.y), pack2(w1.z, w1.w) };
        float a[8] = {a0.x, a0.y, a0.z, a0.w, a1.x, a1.y, a1.z, a1.w};
        #pragma unroll
        for (int ri = 0; ri < 8; ri++) {
            unsigned long long av = pack2(a[ri], a[ri]);
            #pragma unroll
            for (int cj = 0; cj < 4; cj++) fma2(acc[ri][cj], av, w[cj]);
        }
    }

    #pragma unroll
    for (int ri = 0; ri < 8; ri++) {
        float p[ADIM];
        #pragma unroll
        for (int a = 0; a < ADIM; a++) p[a] = 0.f;
        #pragma unroll
        for (int cj = 0; cj < 4; cj++) {
            float2 q = unpack2(acc[ri][cj]);
            q.x = fmaxf(q.x, 0.f);
            q.y = fmaxf(q.y, 0.f);
            const float* wa = &sW2[(c0 + 2 * cj) * ADIM];
            #pragma unroll
            for (int a = 0; a < ADIM; a++)
                p[a] += q.x * wa[a] + q.y * wa[ADIM + a];
        }
        #pragma unroll
        for (int a = 0; a < ADIM; a++) {
            p[a] += __shfl_xor_sync(0xffffffffu, p[a], 8);
            p[a] += __shfl_xor_sync(0xffffffffu, p[a], 16);
        }
        if (lane < 8) {
            int row = r0 + ri;
            #pragma unroll
            for (int a = 0; a < ADIM; a++)
                sOut[wrp * 640 + row * ADIM + a] = p[a];
        }
    }
    __syncthreads();

    for (int idx = tid; idx < 64 * ADIM; idx += 256) {
        float v = 0.f;
        #pragma unroll
        for (int w = 0; w < 8; w++) v += sOut[w * 640 + idx];
        int row = idx / ADIM, a = idx - row * ADIM;
        int node = base + row;
        if (node < N_NODES) out[(size_t)node * ADIM + a] = v + sB2[a];
    }
}

// ---- pre-created side stream + events (no device memory involved) ----
static cudaStream_t g_sideStream;
static cudaEvent_t  g_evFork, g_evJoin;
namespace {
struct StreamInit {
    StreamInit() {
        cudaStreamCreateWithFlags(&g_sideStream, cudaStreamNonBlocking);
        cudaEventCreateWithFlags(&g_evFork, cudaEventDisableTiming);
        cudaEventCreateWithFlags(&g_evJoin, cudaEventDisableTiming);
    }
};
static StreamInit g_streamInit;
}

extern "C" void kernel_launch(void* const* d_in, const int* in_sizes, int n_in,
                              void* d_out, int out_size) {
    const float* x  = (const float*)d_in[0];
    const void*  ei = d_in[1];
    const float* We = (const float*)d_in[2];
    const float* be = (const float*)d_in[3];
    const float* Wg = (const float*)d_in[4];
    const float* bg = (const float*)d_in[5];
    const float* W1 = (const float*)d_in[6];
    const float* b1 = (const float*)d_in[7];
    const float* W2 = (const float*)d_in[8];
    const float* b2 = (const float*)d_in[9];
    float* out = (float*)d_out;

    const size_t smemA = (size_t)(16384 + 2 * 128 * XT_S + 128) * sizeof(float);
    const size_t smemC = (size_t)(32768 + 128 * HT_S + 2560 + 256 + 16 + 5120) * sizeof(float);
    cudaFuncSetAttribute(k_fused1, cudaFuncAttributeMaxDynamicSharedMemorySize, (int)smemA);
    cudaFuncSetAttribute(k_fused2, cudaFuncAttributeMaxDynamicSharedMemorySize, (int)smemC);

    // fork: fused1 (independent GEMM) runs on side stream, sort chain on main stream
    cudaEventRecord(g_evFork, 0);
    cudaStreamWaitEvent(g_sideStream, g_evFork, 0);
    k_fused1<<<(N_NODES + 127) / 128, 256, smemA, g_sideStream>>>(x, We, be, Wg);
    cudaEventRecord(g_evJoin, g_sideStream);

    k_pre<<<98, 1024>>>((const int*)ei);
    k_hist<<<(N_EDGES + 255) / 256, 256>>>(ei);
    k_scanA<<<NCHUNKS, 256>>>();
    k_scanB<<<1, 128>>>();
    k_scanC<<<NCHUNKS, 256>>>();
    k_permute<<<(N_EDGES + 255) / 256, 256>>>(ei);

    // join: aggregate needs both fused1 (xw) and the sort chain
    cudaStreamWaitEvent(0, g_evJoin, 0);
    k_aggregate<<<(N_NODES * 32 + 255) / 256, 256>>>(bg);
    k_fused2<<<(N_NODES + 63) / 64, 256, smemC>>>(W1, b1, W2, b2, out);
}

// round 12
// speedup vs baseline: 1.6205x; 1.0251x over previous
#include <cuda_runtime.h>
#include <cuda_bf16.h>
#include <cstdint>

#define N_NODES 100000
#define N_EDGES 3200000
#define F 128
#define HQ 256
#define ADIM 10
#define NCHUNKS 98   // ceil(100000/1024)

// Scratch (static __device__ arrays: allocation-free per harness rules)
__device__ __align__(16) float g_xw[(size_t)N_NODES * F];          // fp32 xw (self term)
__device__ __align__(16) __nv_bfloat16 g_xwh[(size_t)N_NODES * F]; // bf16 xw (gathers)
__device__ __align__(16) float g_h2[(size_t)N_NODES * F];          // relu(gcn output)
__device__ float g_dinv[N_NODES];
__device__ int   g_cnt[N_NODES];
__device__ int   g_start[N_NODES + 1];
__device__ int   g_cursor[N_NODES];
__device__ int   g_src[N_EDGES];
__device__ int   g_chunksum[NCHUNKS];
__device__ int   g_chunkoff[NCHUNKS];
__device__ int   g_is64;

// ---- packed f32x2 helpers (Blackwell FFMA2 path) ----
static __device__ __forceinline__ unsigned long long pack2(float lo, float hi) {
    unsigned long long r;
    asm("mov.b64 %0, {%1, %2};" : "=l"(r) : "f"(lo), "f"(hi));
    return r;
}
static __device__ __forceinline__ void fma2(unsigned long long& d,
                                            unsigned long long a,
                                            unsigned long long b) {
    asm("fma.rn.f32x2 %0, %1, %2, %0;" : "+l"(d) : "l"(a), "l"(b));
}
static __device__ __forceinline__ float2 unpack2(unsigned long long v) {
    float2 f;
    asm("mov.b64 {%0, %1}, %2;" : "=f"(f.x), "=f"(f.y) : "l"(v));
    return f;
}

static __device__ __forceinline__ int eidx(const void* ei, int is64, long long pos) {
    return is64 ? (int)((const long long*)ei)[pos] : ((const int*)ei)[pos];
}

// ---- pre: dtype detect (block 0, warp 0) + zero histogram counters ----
__global__ void k_pre(const int* __restrict__ ei) {
    if (blockIdx.x == 0 && threadIdx.x < 32) {
        int v = ei[2 * threadIdx.x + 1];
        unsigned m = __ballot_sync(0xffffffffu, v != 0);
        if (threadIdx.x == 0) g_is64 = (m == 0) ? 1 : 0;
    }
    int i = blockIdx.x * blockDim.x + threadIdx.x;
    int stride = gridDim.x * blockDim.x;
    for (; i < N_NODES; i += stride) g_cnt[i] = 0;
}

// ---- histogram of dst (doubles as in-degree count) ----
__global__ void k_hist(const void* __restrict__ ei) {
    int is64 = g_is64;
    int e = blockIdx.x * blockDim.x + threadIdx.x;
    if (e < N_EDGES) atomicAdd(&g_cnt[eidx(ei, is64, (long long)N_EDGES + e)], 1);
}

// ---- scan stage A: per-1024-chunk sums; also dinv = rsqrt(cnt+1) ----
__global__ void k_scanA() {
    __shared__ int wsum[8];
    int t = threadIdx.x;
    int base = blockIdx.x * 1024 + t * 4;
    int s = 0;
    #pragma unroll
    for (int i = 0; i < 4; i++) {
        int idx = base + i;
        if (idx < N_NODES) {
            int c = g_cnt[idx];
            s += c;
            g_dinv[idx] = rsqrtf((float)(c + 1));
        }
    }
    #pragma unroll
    for (int o = 16; o > 0; o >>= 1) s += __shfl_down_sync(0xffffffffu, s, o);
    if ((t & 31) == 0) wsum[t >> 5] = s;
    __syncthreads();
    if (t == 0) {
        int tot = 0;
        #pragma unroll
        for (int w = 0; w < 8; w++) tot += wsum[w];
        g_chunksum[blockIdx.x] = tot;
    }
}

// ---- scan stage B: exclusive scan of chunk sums ----
__global__ void k_scanB() {
    __shared__ int sv[NCHUNKS];
    int t = threadIdx.x;
    if (t < NCHUNKS) sv[t] = g_chunksum[t];
    __syncthreads();
    if (t == 0) {
        int acc = 0;
        for (int b = 0; b < NCHUNKS; b++) { int x = sv[b]; sv[b] = acc; acc += x; }
        g_start[N_NODES] = acc;
    }
    __syncthreads();
    if (t < NCHUNKS) g_chunkoff[t] = sv[t];
}

// ---- scan stage C: within-chunk exclusive scan -> start, cursor ----
__global__ void k_scanC() {
    __shared__ int wsum[8];
    int t = threadIdx.x;
    int lane = t & 31, wid = t >> 5;
    int base = blockIdx.x * 1024 + t * 4;
    int v[4];
    int s = 0;
    #pragma unroll
    for (int i = 0; i < 4; i++) {
        int idx = base + i;
        v[i] = (idx < N_NODES) ? g_cnt[idx] : 0;
        s += v[i];
    }
    int inc = s;
    #pragma unroll
    for (int o = 1; o < 32; o <<= 1) {
        int n = __shfl_up_sync(0xffffffffu, inc, o);
        if (lane >= o) inc += n;
    }
    if (lane == 31) wsum[wid] = inc;
    __syncthreads();
    if (t == 0) {
        int acc = 0;
        #pragma unroll
        for (int w = 0; w < 8; w++) { int x = wsum[w]; wsum[w] = acc; acc += x; }
    }
    __syncthreads();
    int excl = inc - s + wsum[wid] + g_chunkoff[blockIdx.x];
    #pragma unroll
    for (int i = 0; i < 4; i++) {
        int idx = base + i;
        if (idx < N_NODES) { g_start[idx] = excl; g_cursor[idx] = excl; }
        excl += v[i];
    }
}

// ---- permute edges into dst-grouped order ----
__global__ void k_permute(const void* __restrict__ ei) {
    int is64 = g_is64;
    int e = blockIdx.x * blockDim.x + threadIdx.x;
    if (e < N_EDGES) {
        int s = eidx(ei, is64, e);
        int d = eidx(ei, is64, (long long)N_EDGES + e);
        int pos = atomicAdd(&g_cursor[d], 1);
        g_src[pos] = s;
    }
}

// ==================== fused1: xw = relu(x@We + be) @ Wg (fp32 + bf16 copies) ====================
#define XT_S 132

__global__ void __launch_bounds__(256, 1)
k_fused1(const float* __restrict__ x, const float* __restrict__ We,
         const float* __restrict__ be, const float* __restrict__ Wg) {
    extern __shared__ float smem[];
    float* sW  = smem;                    // 128*128
    float* sXT = smem + 16384;            // 128 * XT_S
    float* sHT = sXT + 128 * XT_S;        // 128 * XT_S
    float* sBe = sHT + 128 * XT_S;        // 128

    const int tid = threadIdx.x;
    const int base = blockIdx.x * 128;

    for (int idx = tid; idx < 16384; idx += 256) sW[idx] = We[idx];
    if (tid < 128) sBe[tid] = be[tid];
    for (int idx = tid; idx < 128 * F; idx += 256) {
        int r = idx >> 7, c = idx & 127;
        int node = base + r;
        sXT[c * XT_S + r] = (node < N_NODES) ? x[(size_t)node * F + c] : 0.f;
    }
    __syncthreads();

    const int tr = tid & 15, tc = tid >> 4;
    const int r0 = tr * 8, c0 = tc * 8;

    unsigned long long acc[8][4];
    #pragma unroll
    for (int ri = 0; ri < 8; ri++)
        #pragma unroll
        for (int cj = 0; cj < 4; cj++)
            acc[ri][cj] = pack2(sBe[c0 + 2 * cj], sBe[c0 + 2 * cj + 1]);

    #pragma unroll 4
    for (int k = 0; k < F; k++) {
        float4 a0 = *(const float4*)&sXT[k * XT_S + r0];
        float4 a1 = *(const float4*)&sXT[k * XT_S + r0 + 4];
        float4 w0 = *(const float4*)&sW[k * F + c0];
        float4 w1 = *(const float4*)&sW[k * F + c0 + 4];
        unsigned long long w[4] = { pack2(w0.x, w0.y), pack2(w0.z, w0.w),
                                    pack2(w1.x, w1.y), pack2(w1.z, w1.w) };
        float a[8] = {a0.x, a0.y, a0.z, a0.w, a1.x, a1.y, a1.z, a1.w};
        #pragma unroll
        for (int ri = 0; ri < 8; ri++) {
            unsigned long long av = pack2(a[ri], a[ri]);
            #pragma unroll
            for (int cj = 0; cj < 4; cj++) fma2(acc[ri][cj], av, w[cj]);
        }
    }

    #pragma unroll
    for (int cj = 0; cj < 4; cj++) {
        float2 v[8];
        #pragma unroll
        for (int ri = 0; ri < 8; ri++) v[ri] = unpack2(acc[ri][cj]);
        int c = c0 + 2 * cj;
        *(float4*)&sHT[c * XT_S + r0] =
            make_float4(fmaxf(v[0].x, 0.f), fmaxf(v[1].x, 0.f),
                        fmaxf(v[2].x, 0.f), fmaxf(v[3].x, 0.f));
        *(float4*)&sHT[c * XT_S + r0 + 4] =
            make_float4(fmaxf(v[4].x, 0.f), fmaxf(v[5].x, 0.f),
                        fmaxf(v[6].x, 0.f), fmaxf(v[7].x, 0.f));
        *(float4*)&sHT[(c + 1) * XT_S + r0] =
            make_float4(fmaxf(v[0].y, 0.f), fmaxf(v[1].y, 0.f),
                        fmaxf(v[2].y, 0.f), fmaxf(v[3].y, 0.f));
        *(float4*)&sHT[(c + 1) * XT_S + r0 + 4] =
            make_float4(fmaxf(v[4].y, 0.f), fmaxf(v[5].y, 0.f),
                        fmaxf(v[6].y, 0.f), fmaxf(v[7].y, 0.f));
    }
    __syncthreads();
    for (int idx = tid; idx < 16384; idx += 256) sW[idx] = Wg[idx];
    __syncthreads();

    #pragma unroll
    for (int ri = 0; ri < 8; ri++)
        #pragma unroll
        for (int cj = 0; cj < 4; cj++) acc[ri][cj] = 0ULL;

    #pragma unroll 4
    for (int k = 0; k < F; k++) {
        float4 a0 = *(const float4*)&sHT[k * XT_S + r0];
        float4 a1 = *(const float4*)&sHT[k * XT_S + r0 + 4];
        float4 w0 = *(const float4*)&sW[k * F + c0];
        float4 w1 = *(const float4*)&sW[k * F + c0 + 4];
        unsigned long long w[4] = { pack2(w0.x, w0.y), pack2(w0.z, w0.w),
                                    pack2(w1.x, w1.y), pack2(w1.z, w1.w) };
        float a[8] = {a0.x, a0.y, a0.z, a0.w, a1.x, a1.y, a1.z, a1.w};
        #pragma unroll
        for (int ri = 0; ri < 8; ri++) {
            unsigned long long av = pack2(a[ri], a[ri]);
            #pragma unroll
            for (int cj = 0; cj < 4; cj++) fma2(acc[ri][cj], av, w[cj]);
        }
    }

    #pragma unroll
    for (int ri = 0; ri < 8; ri++) {
        int node = base + r0 + ri;
        if (node < N_NODES) {
            float* dst = &g_xw[(size_t)node * F + c0];
            *(ulonglong2*)(dst)     = make_ulonglong2(acc[ri][0], acc[ri][1]);
            *(ulonglong2*)(dst + 4) = make_ulonglong2(acc[ri][2], acc[ri][3]);
            // bf16 copy: 8 cols -> 4x bfloat162 = one 16B store
            float2 p0 = unpack2(acc[ri][0]);
            float2 p1 = unpack2(acc[ri][1]);
            float2 p2 = unpack2(acc[ri][2]);
            float2 p3 = unpack2(acc[ri][3]);
            __nv_bfloat162 b0 = __float22bfloat162_rn(p0);
            __nv_bfloat162 b1 = __float22bfloat162_rn(p1);
            __nv_bfloat162 b2 = __float22bfloat162_rn(p2);
            __nv_bfloat162 b3 = __float22bfloat162_rn(p3);
            uint4 pk;
            pk.x = *reinterpret_cast<unsigned*>(&b0);
            pk.y = *reinterpret_cast<unsigned*>(&b1);
            pk.z = *reinterpret_cast<unsigned*>(&b2);
            pk.w = *reinterpret_cast<unsigned*>(&b3);
            *reinterpret_cast<uint4*>(&g_xwh[(size_t)node * F + c0]) = pk;
        }
    }
}

// ============ aggregate: warp-per-node, 2 edges per LDG.128 (16-lane sub-groups) ============
// Full bf16 row (128 feats = 256B) = 16 lanes x uint4. sub = lane>>4 handles
// edges j0+sub, j0+sub+2, ... Each lane accumulates 8 features in fp32;
// sub-groups merged via shfl_xor(16) at the end.
__global__ void __launch_bounds__(256)
k_aggregate(const float* __restrict__ bg) {
    int warp = (blockIdx.x * blockDim.x + threadIdx.x) >> 5;
    int lane = threadIdx.x & 31;
    if (warp >= N_NODES) return;

    const int sub  = lane >> 4;
    const int slot = lane & 15;
    const uint4* xh = reinterpret_cast<const uint4*>(g_xwh);  // 16 x uint4 per row

    int j0 = g_start[warp], j1 = g_start[warp + 1];

    float a0[8], a1[8];
    #pragma unroll
    for (int f = 0; f < 8; f++) { a0[f] = 0.f; a1[f] = 0.f; }

    int j = j0 + sub;
    // 4 edges per sub-group per iteration (8 edges/warp), 4 independent LDG.128/lane
    for (; j + 6 < j1; j += 8) {
        int s0 = __ldg(&g_src[j]);
        int s1 = __ldg(&g_src[j + 2]);
        int s2 = __ldg(&g_src[j + 4]);
        int s3 = __ldg(&g_src[j + 6]);
        float c0 = __ldg(&g_dinv[s0]);
        float c1 = __ldg(&g_dinv[s1]);
        float c2 = __ldg(&g_dinv[s2]);
        float c3 = __ldg(&g_dinv[s3]);
        uint4 r0 = __ldg(&xh[(size_t)s0 * 16 + slot]);
        uint4 r1 = __ldg(&xh[(size_t)s1 * 16 + slot]);
        uint4 r2 = __ldg(&xh[(size_t)s2 * 16 + slot]);
        uint4 r3 = __ldg(&xh[(size_t)s3 * 16 + slot]);
        const uint4  rv[4] = {r0, r1, r2, r3};
        const float  cv[4] = {c0, c1, c2, c3};
        #pragma unroll
        for (int u = 0; u < 4; u++) {
            const unsigned uw[4] = {rv[u].x, rv[u].y, rv[u].z, rv[u].w};
            float c = cv[u];
            float* a = (u & 1) ? a1 : a0;
            #pragma unroll
            for (int q = 0; q < 4; q++) {
                __nv_bfloat162 p = *reinterpret_cast<const __nv_bfloat162*>(&uw[q]);
                float2 f2 = __bfloat1622float2(p);
                a[2 * q]     += f2.x * c;
                a[2 * q + 1] += f2.y * c;
            }
        }
    }
    for (; j < j1; j += 2) {
        int s = __ldg(&g_src[j]);
        float c = __ldg(&g_dinv[s]);
        uint4 r = __ldg(&xh[(size_t)s * 16 + slot]);
        const unsigned uw[4] = {r.x, r.y, r.z, r.w};
        #pragma unroll
        for (int q = 0; q < 4; q++) {
            __nv_bfloat162 p = *reinterpret_cast<const __nv_bfloat162*>(&uw[q]);
            float2 f2 = __bfloat1622float2(p);
            a0[2 * q]     += f2.x * c;
            a0[2 * q + 1] += f2.y * c;
        }
    }

    float acc[8];
    #pragma unroll
    for (int f = 0; f < 8; f++) {
        float v = a0[f] + a1[f];
        v += __shfl_xor_sync(0xffffffffu, v, 16);
        acc[f] = v;
    }

    if (sub == 0) {
        float dd = g_dinv[warp];
        float dd2 = dd * dd;
        const float4* xw4 = reinterpret_cast<const float4*>(g_xw);
        float4 self0 = __ldg(&xw4[(size_t)warp * 32 + slot * 2]);
        float4 self1 = __ldg(&xw4[(size_t)warp * 32 + slot * 2 + 1]);
        float4 bg0 = *reinterpret_cast<const float4*>(&bg[slot * 8]);
        float4 bg1 = *reinterpret_cast<const float4*>(&bg[slot * 8 + 4]);
        float4 h0, h1;
        h0.x = fmaxf(dd * acc[0] + dd2 * self0.x + bg0.x, 0.f);
        h0.y = fmaxf(dd * acc[1] + dd2 * self0.y + bg0.y, 0.f);
        h0.z = fmaxf(dd * acc[2] + dd2 * self0.z + bg0.z, 0.f);
        h0.w = fmaxf(dd * acc[3] + dd2 * self0.w + bg0.w, 0.f);
        h1.x = fmaxf(dd * acc[4] + dd2 * self1.x + bg1.x, 0.f);
        h1.y = fmaxf(dd * acc[5] + dd2 * self1.y + bg1.y, 0.f);
        h1.z = fmaxf(dd * acc[6] + dd2 * self1.z + bg1.z, 0.f);
        h1.w = fmaxf(dd * acc[7] + dd2 * self1.w + bg1.w, 0.f);
        float4* h2 = reinterpret_cast<float4*>(g_h2);
        h2[(size_t)warp * 32 + slot * 2]     = h0;
        h2[(size_t)warp * 32 + slot * 2 + 1] = h1;
    }
}

// ==================== fused2: out = relu(h2@W1+b1)@W2+b2 ====================
#define HT_S 68

__global__ void __launch_bounds__(256, 1)
k_fused2(const float* __restrict__ W1, const float* __restrict__ b1,
         const float* __restrict__ W2, const float* __restrict__ b2,
         float* __restrict__ out) {
    extern __shared__ float smem[];
    float* sW1  = smem;                   // 32768
    float* sHT  = sW1 + 32768;            // 128 * HT_S
    float* sW2  = sHT + 128 * HT_S;       // 2560
    float* sB1  = sW2 + 2560;             // 256
    float* sB2  = sB1 + 256;              // 16
    float* sOut = sB2 + 16;               // 8 * 640

    const int tid = threadIdx.x;
    const int base = blockIdx.x * 64;

    for (int idx = tid; idx < 32768; idx += 256) sW1[idx] = W1[idx];
    for (int idx = tid; idx < 2560; idx += 256) sW2[idx] = W2[idx];
    sB1[tid] = b1[tid];
    if (tid < ADIM) sB2[tid] = b2[tid];

    for (int idx = tid; idx < 64 * F; idx += 256) {
        int r = idx >> 7, c = idx & 127;
        int node = base + r;
        sHT[c * HT_S + r] = (node < N_NODES) ? g_h2[(size_t)node * F + c] : 0.f;
    }
    __syncthreads();

    const int tr = tid & 7, tc = tid >> 3;
    const int r0 = tr * 8, c0 = tc * 8;
    const int lane = tid & 31, wrp = tid >> 5;

    unsigned long long acc[8][4];
    #pragma unroll
    for (int ri = 0; ri < 8; ri++)
        #pragma unroll
        for (int cj = 0; cj < 4; cj++)
            acc[ri][cj] = pack2(sB1[c0 + 2 * cj], sB1[c0 + 2 * cj + 1]);

    #pragma unroll 4
    for (int k = 0; k < F; k++) {
        float4 a0 = *(const float4*)&sHT[k * HT_S + r0];
        float4 a1 = *(const float4*)&sHT[k * HT_S + r0 + 4];
        float4 w0 = *(const float4*)&sW1[k * HQ + c0];
        float4 w1 = *(const float4*)&sW1[k * HQ + c0 + 4];
        unsigned long long w[4] = { pack2(w0.x, w0.y), pack2(w0.z, w0.w),
                                    pack2(w1.x, w1.y), pack2(w1.z, w1.w) };
        float a[8] = {a0.x, a0.y, a0.z, a0.w, a1.x, a1.y, a1.z, a1.w};
        #pragma unroll
        for (int ri = 0; ri < 8; ri++) {
            unsigned long long av = pack2(a[ri], a[ri]);
            #pragma unroll
            for (int cj = 0; cj < 4; cj++) fma2(acc[ri][cj], av, w[cj]);
        }
    }

    #pragma unroll
    for (int ri = 0; ri < 8; ri++) {
        float p[ADIM];
        #pragma unroll
        for (int a = 0; a < ADIM; a++) p[a] = 0.f;
        #pragma unroll
        for (int cj = 0; cj < 4; cj++) {
            float2 q = unpack2(acc[ri][cj]);
            q.x = fmaxf(q.x, 0.f);
            q.y = fmaxf(q.y, 0.f);
            const float* wa = &sW2[(c0 + 2 * cj) * ADIM];
            #pragma unroll
            for (int a = 0; a < ADIM; a++)
                p[a] += q.x * wa[a] + q.y * wa[ADIM + a];
        }
        #pragma unroll
        for (int a = 0; a < ADIM; a++) {
            p[a] += __shfl_xor_sync(0xffffffffu, p[a], 8);
            p[a] += __shfl_xor_sync(0xffffffffu, p[a], 16);
        }
        if (lane < 8) {
            int row = r0 + ri;
            #pragma unroll
            for (int a = 0; a < ADIM; a++)
                sOut[wrp * 640 + row * ADIM + a] = p[a];
        }
    }
    __syncthreads();

    for (int idx = tid; idx < 64 * ADIM; idx += 256) {
        float v = 0.f;
        #pragma unroll
        for (int w = 0; w < 8; w++) v += sOut[w * 640 + idx];
        int row = idx / ADIM, a = idx - row * ADIM;
        int node = base + row;
        if (node < N_NODES) out[(size_t)node * ADIM + a] = v + sB2[a];
    }
}

// ---- pre-created side stream + events (no device memory involved) ----
static cudaStream_t g_sideStream;
static cudaEvent_t  g_evFork, g_evJoin;
namespace {
struct StreamInit {
    StreamInit() {
        cudaStreamCreateWithFlags(&g_sideStream, cudaStreamNonBlocking);
        cudaEventCreateWithFlags(&g_evFork, cudaEventDisableTiming);
        cudaEventCreateWithFlags(&g_evJoin, cudaEventDisableTiming);
    }
};
static StreamInit g_streamInit;
}

extern "C" void kernel_launch(void* const* d_in, const int* in_sizes, int n_in,
                              void* d_out, int out_size) {
    const float* x  = (const float*)d_in[0];
    const void*  ei = d_in[1];
    const float* We = (const float*)d_in[2];
    const float* be = (const float*)d_in[3];
    const float* Wg = (const float*)d_in[4];
    const float* bg = (const float*)d_in[5];
    const float* W1 = (const float*)d_in[6];
    const float* b1 = (const float*)d_in[7];
    const float* W2 = (const float*)d_in[8];
    const float* b2 = (const float*)d_in[9];
    float* out = (float*)d_out;

    const size_t smemA = (size_t)(16384 + 2 * 128 * XT_S + 128) * sizeof(float);
    const size_t smemC = (size_t)(32768 + 128 * HT_S + 2560 + 256 + 16 + 5120) * sizeof(float);
    cudaFuncSetAttribute(k_fused1, cudaFuncAttributeMaxDynamicSharedMemorySize, (int)smemA);
    cudaFuncSetAttribute(k_fused2, cudaFuncAttributeMaxDynamicSharedMemorySize, (int)smemC);

    // fork: fused1 (independent GEMM) runs on side stream, sort chain on main stream
    cudaEventRecord(g_evFork, 0);
    cudaStreamWaitEvent(g_sideStream, g_evFork, 0);
    k_fused1<<<(N_NODES + 127) / 128, 256, smemA, g_sideStream>>>(x, We, be, Wg);
    cudaEventRecord(g_evJoin, g_sideStream);

    k_pre<<<98, 1024>>>((const int*)ei);
    k_hist<<<(N_EDGES + 255) / 256, 256>>>(ei);
    k_scanA<<<NCHUNKS, 256>>>();
    k_scanB<<<1, 128>>>();
    k_scanC<<<NCHUNKS, 256>>>();
    k_permute<<<(N_EDGES + 255) / 256, 256>>>(ei);

    // join: aggregate needs both fused1 (xw) and the sort chain
    cudaStreamWaitEvent(0, g_evJoin, 0);
    k_aggregate<<<(N_NODES * 32 + 255) / 256, 256>>>(bg);
    k_fused2<<<(N_NODES + 63) / 64, 256, smemC>>>(W1, b1, W2, b2, out);
}